// round 1
// baseline (speedup 1.0000x reference)
#include <cuda_runtime.h>
#include <math.h>

#define Ntot 48000
#define Hh   128
#define NPRc 3000
#define EPRc 6000
#define NC   512      // C columns: [0,384) iou_x, [384,512) wf_x

// static scratch (no allocations allowed)
__device__ float g_C[(size_t)Ntot * NC];   // 98.3 MB
__device__ float g_c[(size_t)Ntot * Hh];   // 24.6 MB

union F2U { float2 f; unsigned long long u; };

__device__ __forceinline__ float2 ffma2(float2 a, float2 b, float2 c) {
    F2U A, B, Cc, D;
    A.f = a; B.f = b; Cc.f = c;
    asm("fma.rn.f32x2 %0, %1, %2, %3;" : "=l"(D.u) : "l"(A.u), "l"(B.u), "l"(Cc.u));
    return D.f;
}

__device__ __forceinline__ float sigf(float x) { return 1.0f / (1.0f + expf(-x)); }

// ---------------------------------------------------------------------------
// Precompute C[n][0:384] = x[n] @ W_iou^T, C[n][384:512] = x[n] @ W_f^T
// grid 148, 256 thr. Thread owns 2 output cols (t, t+256), rows tiled by 16.
// ---------------------------------------------------------------------------
#define PRE_RPB 325
#define PRE_SUB 16

__global__ __launch_bounds__(256) void k_pre(const float* __restrict__ x,
                                             const float* __restrict__ W_iou,
                                             const float* __restrict__ W_f) {
    __shared__ float xs[PRE_SUB][128];
    int t = threadIdx.x;
    const float* r0p = W_iou + t * 128;                                   // col t   (<384)
    const float* r1p = (t < 128) ? (W_iou + (256 + t) * 128)              // col 256+t
                                 : (W_f + (t - 128) * 128);               // wf col
    int rowEnd = min((int)(blockIdx.x + 1) * PRE_RPB, Ntot);
    for (int rs = blockIdx.x * PRE_RPB; rs < rowEnd; rs += PRE_SUB) {
        int nr = min(PRE_SUB, rowEnd - rs);
        __syncthreads();
        for (int idx = t; idx < nr * 32; idx += 256) {
            int rr = idx >> 5, q = idx & 31;
            ((float4*)xs[rr])[q] = ((const float4*)(x + (size_t)(rs + rr) * 128))[q];
        }
        __syncthreads();
        float2 a0[PRE_SUB], a1[PRE_SUB];
#pragma unroll
        for (int r = 0; r < PRE_SUB; r++) { a0[r] = make_float2(0.f, 0.f); a1[r] = make_float2(0.f, 0.f); }
#pragma unroll 1
        for (int k0 = 0; k0 < 128; k0 += 16) {
            float2 w0[8], w1[8];
#pragma unroll
            for (int q = 0; q < 4; q++) {
                float4 v0 = *(const float4*)(r0p + k0 + 4 * q);
                float4 v1 = *(const float4*)(r1p + k0 + 4 * q);
                w0[2*q] = make_float2(v0.x, v0.y); w0[2*q+1] = make_float2(v0.z, v0.w);
                w1[2*q] = make_float2(v1.x, v1.y); w1[2*q+1] = make_float2(v1.z, v1.w);
            }
#pragma unroll
            for (int kk = 0; kk < 8; kk++) {
#pragma unroll
                for (int r = 0; r < PRE_SUB; r++) {
                    float2 xv = *(const float2*)&xs[r][k0 + 2 * kk];
                    a0[r] = ffma2(w0[kk], xv, a0[r]);
                    a1[r] = ffma2(w1[kk], xv, a1[r]);
                }
            }
        }
        for (int r = 0; r < nr; r++) {
            g_C[(size_t)(rs + r) * NC + t]       = a0[r].x + a0[r].y;
            g_C[(size_t)(rs + r) * NC + 256 + t] = a1[r].x + a1[r].y;
        }
    }
}

// ---------------------------------------------------------------------------
// Round 0: leaves. iou_mid = 0, c = 0.
// ---------------------------------------------------------------------------
__global__ __launch_bounds__(256) void k_round0(float* __restrict__ h,
                                                const int* __restrict__ order0,
                                                const float* __restrict__ b_iou) {
    int idx = blockIdx.x * 256 + threadIdx.x;
    if (idx >= NPRc * Hh) return;
    int j = idx >> 7, m = idx & 127;
    int node = order0[j];
    const float* Cp = g_C + (size_t)node * NC;
    float gi = Cp[m]       + b_iou[m];
    float go = Cp[128 + m] + b_iou[128 + m];
    float gu = Cp[256 + m] + b_iou[256 + m];
    float ct = sigf(gi) * tanhf(gu);
    g_c[(size_t)node * Hh + m] = ct;
    h[(size_t)node * Hh + m]   = sigf(go) * tanhf(ct);
}

// ---------------------------------------------------------------------------
// One topological round, fully fused. grid 148, 256 thr, 21 parents/block.
// Per parent: gsum = he2_a + he2_b (dense 256), iou = U_iou @ gsum (no label
// selects!); f_a = U_f @ he2_a, f_b = U_f @ he2_b (dense-256, zero half).
// Outputs per parent: 640 = 384 iou + 128 fa + 128 fb.
//   t<128 (warps 0-3): cols t (iou-i), 256+t (iou-u), fb[t]     -> 3 accs
//   t>=128 (warps 4-7): cols t (iou-o), fa[t-128]               -> 2 accs
// (3+2 split balances per-SMSP: each SMSP hosts one heavy + one light warp)
// ---------------------------------------------------------------------------
#define PPB  21
#define PSUB 8

__global__ __launch_bounds__(256) void k_round(int ri,
        float* __restrict__ h,
        const float* __restrict__ U_iou, const float* __restrict__ U_f,
        const float* __restrict__ b_iou, const float* __restrict__ b_f,
        const int* __restrict__ edges_r, const float* __restrict__ labels) {
    __shared__ float gs[PSUB * 768];    // per parent: [0,256) gsum | [256,512) he2_a | [512,768) he2_b
    __shared__ float epi[PSUB * 640];   // per parent: [0,384) iou | [384,512) z_fa | [512,640) z_fb
    __shared__ int s_child[2 * PSUB];
    __shared__ int s_lab[2 * PSUB];
    __shared__ int s_par[PSUB];

    int t = threadIdx.x;
    const int*   e_src   = edges_r + ri * 2 * EPRc;
    const int*   e_child = e_src + EPRc;
    const float* labp    = labels + ri * EPRc;

    const float *rowA0 = U_iou, *rowA1 = U_iou, *rowA2 = U_f;
    const float *rowB0 = U_iou, *rowB1 = U_f;
    if (t < 128) {
        rowA0 = U_iou + t * 256;
        rowA1 = U_iou + (256 + t) * 256;
        rowA2 = U_f + t * 256;
    } else {
        rowB0 = U_iou + t * 256;
        rowB1 = U_f + (t - 128) * 256;
    }

    int pend = min((int)(blockIdx.x + 1) * PPB, NPRc);
    for (int ps = blockIdx.x * PPB; ps < pend; ps += PSUB) {
        int np = min(PSUB, pend - ps);
        __syncthreads();   // protect s_* / gs vs previous sub-batch readers
        if (t < 2 * np) {
            int e = 2 * ps + t;
            s_child[t] = e_child[e];
            s_lab[t]   = (labp[e] != 0.0f) ? 1 : 0;
        }
        if (t < np) s_par[t] = e_src[2 * (ps + t)];
        __syncthreads();

        // build he2_a / he2_b  (h in half 'lab', zero elsewhere)
        for (int idx = t; idx < np * 128; idx += 256) {       // 2*np edges * 64 float4
            int e = idx >> 6, q = idx & 63;
            float4 v = make_float4(0.f, 0.f, 0.f, 0.f);
            if ((q >> 5) == s_lab[e])
                v = ((const float4*)(h + (size_t)s_child[e] * Hh))[q & 31];
            int p = e >> 1, eo = e & 1;
            *((float4*)(gs + p * 768 + 256 + eo * 256) + q) = v;
        }
        __syncthreads();
        // gsum = he2_a + he2_b
        for (int idx = t; idx < np * 64; idx += 256) {
            int p = idx >> 6, q = idx & 63;
            float4 a = *((const float4*)(gs + p * 768 + 256) + q);
            float4 b = *((const float4*)(gs + p * 768 + 512) + q);
            *((float4*)(gs + p * 768) + q) = make_float4(a.x + b.x, a.y + b.y, a.z + b.z, a.w + b.w);
        }
        __syncthreads();

        if (t < 128) {
            float2 a0[PSUB], a1[PSUB], a2[PSUB];
#pragma unroll
            for (int p = 0; p < PSUB; p++) { a0[p] = make_float2(0.f,0.f); a1[p] = make_float2(0.f,0.f); a2[p] = make_float2(0.f,0.f); }
#pragma unroll 1
            for (int k0 = 0; k0 < 256; k0 += 16) {
                float2 w0[8], w1[8], w2[8];
#pragma unroll
                for (int q = 0; q < 4; q++) {
                    float4 v0 = *(const float4*)(rowA0 + k0 + 4 * q);
                    float4 v1 = *(const float4*)(rowA1 + k0 + 4 * q);
                    float4 v2 = *(const float4*)(rowA2 + k0 + 4 * q);
                    w0[2*q] = make_float2(v0.x,v0.y); w0[2*q+1] = make_float2(v0.z,v0.w);
                    w1[2*q] = make_float2(v1.x,v1.y); w1[2*q+1] = make_float2(v1.z,v1.w);
                    w2[2*q] = make_float2(v2.x,v2.y); w2[2*q+1] = make_float2(v2.z,v2.w);
                }
#pragma unroll
                for (int kk = 0; kk < 8; kk++) {
#pragma unroll
                    for (int p = 0; p < PSUB; p++) {
                        float2 g0 = *(const float2*)&gs[p * 768 + k0 + 2 * kk];        // gsum
                        float2 g2 = *(const float2*)&gs[p * 768 + 512 + k0 + 2 * kk];  // he2_b
                        a0[p] = ffma2(w0[kk], g0, a0[p]);
                        a1[p] = ffma2(w1[kk], g0, a1[p]);
                        a2[p] = ffma2(w2[kk], g2, a2[p]);
                    }
                }
            }
#pragma unroll
            for (int p = 0; p < PSUB; p++) {
                epi[p * 640 + t]       = a0[p].x + a0[p].y;   // iou col t
                epi[p * 640 + 256 + t] = a1[p].x + a1[p].y;   // iou col 256+t
                epi[p * 640 + 512 + t] = a2[p].x + a2[p].y;   // z_fb[t]
            }
        } else {
            float2 a0[PSUB], a1[PSUB];
#pragma unroll
            for (int p = 0; p < PSUB; p++) { a0[p] = make_float2(0.f,0.f); a1[p] = make_float2(0.f,0.f); }
#pragma unroll 1
            for (int k0 = 0; k0 < 256; k0 += 16) {
                float2 w0[8], w1[8];
#pragma unroll
                for (int q = 0; q < 4; q++) {
                    float4 v0 = *(const float4*)(rowB0 + k0 + 4 * q);
                    float4 v1 = *(const float4*)(rowB1 + k0 + 4 * q);
                    w0[2*q] = make_float2(v0.x,v0.y); w0[2*q+1] = make_float2(v0.z,v0.w);
                    w1[2*q] = make_float2(v1.x,v1.y); w1[2*q+1] = make_float2(v1.z,v1.w);
                }
#pragma unroll
                for (int kk = 0; kk < 8; kk++) {
#pragma unroll
                    for (int p = 0; p < PSUB; p++) {
                        float2 g0 = *(const float2*)&gs[p * 768 + k0 + 2 * kk];        // gsum
                        float2 g1 = *(const float2*)&gs[p * 768 + 256 + k0 + 2 * kk];  // he2_a
                        a0[p] = ffma2(w0[kk], g0, a0[p]);
                        a1[p] = ffma2(w1[kk], g1, a1[p]);
                    }
                }
            }
#pragma unroll
            for (int p = 0; p < PSUB; p++) {
                epi[p * 640 + t]                = a0[p].x + a0[p].y;   // iou col t
                epi[p * 640 + 384 + (t - 128)]  = a1[p].x + a1[p].y;   // z_fa[t-128]
            }
        }
        __syncthreads();

        // epilogue: f gates, c accumulation, node_update
        for (int idx = t; idx < np * Hh; idx += 256) {
            int pl = idx >> 7, m = idx & 127;
            int par = s_par[pl];
            int cA = s_child[2 * pl], cB = s_child[2 * pl + 1];
            const float* Cp = g_C + (size_t)par * NC;
            float gi = Cp[m]       + epi[pl * 640 + m]       + b_iou[m];
            float go = Cp[128 + m] + epi[pl * 640 + 128 + m] + b_iou[128 + m];
            float gu = Cp[256 + m] + epi[pl * 640 + 256 + m] + b_iou[256 + m];
            float fa = sigf(g_C[(size_t)cA * NC + 384 + m] + epi[pl * 640 + 384 + m] + b_f[m]);
            float fb = sigf(g_C[(size_t)cB * NC + 384 + m] + epi[pl * 640 + 512 + m] + b_f[m]);
            float ca = g_c[(size_t)cA * Hh + m]; ca = fminf(fmaxf(ca, -1e14f), 1e14f);
            float cb = g_c[(size_t)cB * Hh + m]; cb = fminf(fmaxf(cb, -1e14f), 1e14f);
            float ct = sigf(gi) * tanhf(gu) + fa * ca + fb * cb;
            g_c[(size_t)par * Hh + m] = ct;
            h[(size_t)par * Hh + m]   = sigf(go) * tanhf(ct);
        }
    }
}

// ---------------------------------------------------------------------------
extern "C" void kernel_launch(void* const* d_in, const int* in_sizes, int n_in,
                              void* d_out, int out_size) {
    const float* x      = (const float*)d_in[0];
    const float* labels = (const float*)d_in[1];   // [15,6000,1]
    const float* W_iou  = (const float*)d_in[2];
    const float* W_f    = (const float*)d_in[3];
    const float* b_iou  = (const float*)d_in[4];
    const float* b_f    = (const float*)d_in[5];
    const float* U_iou  = (const float*)d_in[6];
    const float* U_f    = (const float*)d_in[7];
    const int*   edges  = (const int*)d_in[8];     // [15,2,6000]
    const int*   order0 = (const int*)d_in[9];
    float* h = (float*)d_out;                      // h lives directly in d_out

    k_pre<<<148, 256>>>(x, W_iou, W_f);
    k_round0<<<(NPRc * Hh + 255) / 256, 256>>>(h, order0, b_iou);
    for (int ri = 0; ri < 15; ri++)
        k_round<<<148, 256>>>(ri, h, U_iou, U_f, b_iou, b_f, edges, labels);
}